// round 3
// baseline (speedup 1.0000x reference)
#include <cuda_runtime.h>
#include <cuda_bf16.h>

#define NSKU 100000
#define NWH  5000
#define NSUP 2000
#define EINTRA 400000
#define ECROSS 200000
#define TOTN (4*NSKU + NWH + NSUP)

typedef unsigned long long u64;

// ------------- static scratch (no allocations allowed) -------------
__device__ float g_H[6 * NSKU * 64];      // transformed sku feats per type
__device__ float g_Ss[6 * NSKU * 4];      // src scores per type/head
__device__ float g_SdI[4 * NSKU * 4];     // dst scores, intra types
__device__ float g_Swh[NWH * 4];
__device__ float g_Ssup[NSUP * 4];
__device__ float g_OA[NSKU * 64];
__device__ float g_OBwh[NWH * 64];
__device__ float g_OBsup[NSUP * 64];
__device__ int g_deg[TOTN];
__device__ int g_cur[TOTN];
__device__ int g_rp[4 * (NSKU + 1) + (NWH + 1) + (NSUP + 1)];
__device__ int g_col[4 * EINTRA + 2 * ECROSS];

// ------------- f32x2 helpers -------------
static __device__ __forceinline__ u64 dup2(float x) {
    u64 r; asm("mov.b64 %0, {%1, %1};" : "=l"(r) : "f"(x)); return r;
}
static __device__ __forceinline__ float2 unpack2(u64 v) {
    float2 d; asm("mov.b64 {%0, %1}, %2;" : "=f"(d.x), "=f"(d.y) : "l"(v)); return d;
}
static __device__ __forceinline__ void ffma2(u64& d, u64 a, u64 b) {
    asm("fma.rn.f32x2 %0, %1, %2, %0;" : "+l"(d) : "l"(a), "l"(b));
}

struct EP6 { const int* p[6]; };
struct GP6 { const float* W[6]; const float* a[6]; };

// ------------- CSR pointer resolver -------------
static __device__ __forceinline__ void csr_ptrs(int t, int& N, int& E,
        int*& deg, int*& rp, int*& cur, int*& col) {
    if (t < 4) {
        N = NSKU; E = EINTRA;
        deg = g_deg + t * NSKU; rp = g_rp + t * (NSKU + 1);
        cur = g_cur + t * NSKU; col = g_col + t * EINTRA;
    } else if (t == 4) {
        N = NWH; E = ECROSS;
        deg = g_deg + 4 * NSKU; rp = g_rp + 4 * (NSKU + 1);
        cur = g_cur + 4 * NSKU; col = g_col + 4 * EINTRA;
    } else {
        N = NSUP; E = ECROSS;
        deg = g_deg + 4 * NSKU + NWH; rp = g_rp + 4 * (NSKU + 1) + (NWH + 1);
        cur = g_cur + 4 * NSKU + NWH; col = g_col + 4 * EINTRA + ECROSS;
    }
}

// ------------- CSR build -------------
__global__ void zero_deg_k() {
    int i = blockIdx.x * 256 + threadIdx.x;
    if (i < TOTN) g_deg[i] = 0;
}

__global__ void count_k(EP6 ep) {
    int t = blockIdx.y;
    int N, E; int *deg, *rp, *cur, *col;
    csr_ptrs(t, N, E, deg, rp, cur, col);
    int e = blockIdx.x * 256 + threadIdx.x;
    if (e >= E) return;
    atomicAdd(&deg[ep.p[t][E + e]], 1);
}

__global__ void __launch_bounds__(1024) scan_k() {
    int t = blockIdx.x;
    int N, E; int *deg, *rp, *cur, *col;
    csr_ptrs(t, N, E, deg, rp, cur, col);
    __shared__ int wsum[32];
    __shared__ int s_carry;
    int tid = threadIdx.x, lane = tid & 31, w = tid >> 5;
    if (tid == 0) s_carry = 0;
    __syncthreads();
    int iters = (N + 1023) >> 10;
    for (int it = 0; it < iters; it++) {
        int i = it * 1024 + tid;
        int v = (i < N) ? deg[i] : 0;
        int x = v;
        #pragma unroll
        for (int o = 1; o < 32; o <<= 1) {
            int y = __shfl_up_sync(0xffffffffu, x, o);
            if (lane >= o) x += y;
        }
        if (lane == 31) wsum[w] = x;
        __syncthreads();
        if (w == 0) {
            int s = wsum[lane];
            #pragma unroll
            for (int o = 1; o < 32; o <<= 1) {
                int y = __shfl_up_sync(0xffffffffu, s, o);
                if (lane >= o) s += y;
            }
            wsum[lane] = s;
        }
        __syncthreads();
        int incl = x + (w > 0 ? wsum[w - 1] : 0) + s_carry;
        int excl = incl - v;
        if (i < N) { rp[i] = excl; cur[i] = excl; }
        __syncthreads();
        if (tid == 1023) s_carry = incl;
        __syncthreads();
    }
    if (tid == 0) rp[N] = s_carry;
}

__global__ void fill_k(EP6 ep) {
    int t = blockIdx.y;
    int N, E; int *deg, *rp, *cur, *col;
    csr_ptrs(t, N, E, deg, rp, cur, col);
    int e = blockIdx.x * 256 + threadIdx.x;
    if (e >= E) return;
    int src = ep.p[t][e];
    int dst = ep.p[t][E + e];
    int pos = atomicAdd(&cur[dst], 1);
    col[pos] = src;
}

// ------------- dense phase: H[t] = x_sku @ W[t], fused score epilogue -------------
__global__ void __launch_bounds__(256) gemm6_k(const float* __restrict__ X, GP6 gp) {
    __shared__ __align__(16) float Xs[16][128];
    __shared__ __align__(16) float Ws[16][64];
    int t = blockIdx.y;
    const float* __restrict__ W = gp.W[t];
    const float* __restrict__ av = gp.a[t];
    int tid = threadIdx.x;
    int tc = tid & 15, tr = tid >> 4;
    int m0 = blockIdx.x * 128;

    u64 acc[4][4];
    #pragma unroll
    for (int r = 0; r < 4; r++)
        #pragma unroll
        for (int c = 0; c < 4; c++) acc[r][c] = 0ull;

    for (int kb = 0; kb < 128; kb += 16) {
        #pragma unroll
        for (int q = 0; q < 2; q++) {
            int s = tid * 2 + q;
            int row = s >> 2, j = s & 3;
            int gr = m0 + row;
            float4 v = make_float4(0.f, 0.f, 0.f, 0.f);
            if (gr < NSKU) v = *(const float4*)(X + (size_t)gr * 128 + kb + j * 4);
            Xs[j * 4 + 0][row] = v.x; Xs[j * 4 + 1][row] = v.y;
            Xs[j * 4 + 2][row] = v.z; Xs[j * 4 + 3][row] = v.w;
        }
        {
            int k = tid >> 4, c4 = tid & 15;
            *(float4*)&Ws[k][c4 * 4] = *(const float4*)(W + (size_t)(kb + k) * 64 + c4 * 4);
        }
        __syncthreads();
        #pragma unroll
        for (int kk = 0; kk < 16; kk++) {
            ulonglong2 aa0 = *(const ulonglong2*)&Xs[kk][tr * 8];
            ulonglong2 aa1 = *(const ulonglong2*)&Xs[kk][tr * 8 + 4];
            float4 b4 = *(const float4*)&Ws[kk][tc * 4];
            u64 d0 = dup2(b4.x), d1 = dup2(b4.y), d2 = dup2(b4.z), d3 = dup2(b4.w);
            u64 a2[4] = { aa0.x, aa0.y, aa1.x, aa1.y };
            #pragma unroll
            for (int r = 0; r < 4; r++) {
                ffma2(acc[r][0], a2[r], d0);
                ffma2(acc[r][1], a2[r], d1);
                ffma2(acc[r][2], a2[r], d2);
                ffma2(acc[r][3], a2[r], d3);
            }
        }
        __syncthreads();
    }

    float out[8][4];
    #pragma unroll
    for (int r = 0; r < 4; r++)
        #pragma unroll
        for (int c = 0; c < 4; c++) {
            float2 u = unpack2(acc[r][c]);
            out[2 * r][c] = u.x; out[2 * r + 1][c] = u.y;
        }

    float4 as4 = *(const float4*)(av + (tc & 3) * 4);
    float4 ad4 = *(const float4*)(av + 16 + (tc & 3) * 4);
    float* Ht = g_H + (size_t)t * NSKU * 64;
    float* Sst = g_Ss + (size_t)t * NSKU * 4;
    float* Sdt = (t < 4) ? (g_SdI + (size_t)t * NSKU * 4) : 0;
    int head = tc >> 2;
    #pragma unroll
    for (int r = 0; r < 8; r++) {
        int row = m0 + tr * 8 + r;
        float ps = out[r][0] * as4.x + out[r][1] * as4.y + out[r][2] * as4.z + out[r][3] * as4.w;
        float pd = out[r][0] * ad4.x + out[r][1] * ad4.y + out[r][2] * ad4.z + out[r][3] * ad4.w;
        ps += __shfl_xor_sync(0xffffffffu, ps, 1);
        ps += __shfl_xor_sync(0xffffffffu, ps, 2);
        pd += __shfl_xor_sync(0xffffffffu, pd, 1);
        pd += __shfl_xor_sync(0xffffffffu, pd, 2);
        if (row < NSKU) {
            *(float4*)(Ht + (size_t)row * 64 + tc * 4) =
                make_float4(out[r][0], out[r][1], out[r][2], out[r][3]);
            if ((tc & 3) == 0) {
                Sst[row * 4 + head] = ps;
                if (Sdt) Sdt[row * 4 + head] = pd;
            }
        }
    }
}

// ------------- dst-side scores for cross types (tiny matvec) -------------
__global__ void dstscore_k(const float* __restrict__ X, const float* __restrict__ W,
                           const float* __restrict__ av, int which, int N) {
    float* S = which ? g_Ssup : g_Swh;
    int n = blockIdx.x;
    if (n >= N) return;
    int d = threadIdx.x;               // 0..63
    const float* xr = X + (size_t)n * 128;
    float h = 0.f;
    for (int k = 0; k < 128; k++) h += xr[k] * W[k * 64 + d];
    float p = h * av[16 + (d & 15)];
    #pragma unroll
    for (int o = 1; o < 16; o <<= 1) p += __shfl_xor_sync(0xffffffffu, p, o);
    if ((d & 15) == 0) S[n * 4 + (d >> 4)] = p;
}

// ------------- edge aggregation: one warp per dst node -------------
__global__ void agg_intra_k() {
    int warp = (blockIdx.x * blockDim.x + threadIdx.x) >> 5;
    int lane = threadIdx.x & 31;
    if (warp >= NSKU) return;
    int dst = warp;
    int head = lane >> 3;
    float2 tot = make_float2(0.f, 0.f);
    #pragma unroll
    for (int t = 0; t < 4; t++) {
        const int* rp = g_rp + t * (NSKU + 1);
        const int* col = g_col + t * EINTRA;
        const float* Ss = g_Ss + (size_t)t * NSKU * 4;
        const float* Sd = g_SdI + (size_t)t * NSKU * 4;
        const float* H = g_H + (size_t)t * NSKU * 64;
        float sd = Sd[dst * 4 + head];
        float2 acc = make_float2(0.f, 0.f);
        float den = 0.f;
        int e1 = rp[dst + 1];
        for (int e = rp[dst]; e < e1; e++) {
            int src = __ldg(&col[e]);
            float x = __ldg(&Ss[src * 4 + head]) + sd;
            float el = x > 0.f ? x : (__expf(x) - 1.f);
            float w = __expf(el);
            float2 h = *(const float2*)(H + (size_t)src * 64 + 2 * lane);
            acc.x += w * h.x; acc.y += w * h.y; den += w;
        }
        float inv = 1.f / (den + 1e-12f);
        tot.x += acc.x * inv; tot.y += acc.y * inv;
    }
    *(float2*)(g_OA + (size_t)dst * 64 + 2 * lane) = tot;
}

__global__ void agg_cross_k(int t, int N) {
    int warp = (blockIdx.x * blockDim.x + threadIdx.x) >> 5;
    int lane = threadIdx.x & 31;
    if (warp >= N) return;
    int dst = warp;
    int head = lane >> 3;
    const int* rp = g_rp + 4 * (NSKU + 1) + (t == 5 ? (NWH + 1) : 0);
    const int* col = g_col + 4 * EINTRA + (t == 5 ? ECROSS : 0);
    const float* Ss = g_Ss + (size_t)t * NSKU * 4;
    const float* Sd = (t == 4) ? g_Swh : g_Ssup;
    const float* H = g_H + (size_t)t * NSKU * 64;
    float* Out = (t == 4) ? g_OBwh : g_OBsup;
    float sd = Sd[dst * 4 + head];
    float2 acc = make_float2(0.f, 0.f);
    float den = 0.f;
    int e1 = rp[dst + 1];
    for (int e = rp[dst]; e < e1; e++) {
        int src = __ldg(&col[e]);
        float x = __ldg(&Ss[src * 4 + head]) + sd;
        float el = x > 0.f ? x : (__expf(x) - 1.f);
        float w = __expf(el);
        float2 h = *(const float2*)(H + (size_t)src * 64 + 2 * lane);
        acc.x += w * h.x; acc.y += w * h.y; den += w;
    }
    float inv = 1.f / (den + 1e-12f);
    *(float2*)(Out + (size_t)dst * 64 + 2 * lane) = make_float2(acc.x * inv, acc.y * inv);
}

// ------------- finish: y = [G|X] @ [PW;RW] + b, LayerNorm -------------
__global__ void __launch_bounds__(256) finish_k(
        const float* __restrict__ X, const float* __restrict__ PW,
        const float* __restrict__ RW, const float* __restrict__ pb,
        const float* __restrict__ lg, const float* __restrict__ lb,
        float* __restrict__ out, int N, int which) {
    const float* __restrict__ G = (which == 0) ? g_OA : (which == 1) ? g_OBwh : g_OBsup;
    __shared__ __align__(16) float Xs[16][128];
    __shared__ __align__(16) float Ws[16][64];
    int tid = threadIdx.x, tc = tid & 15, tr = tid >> 4;
    int m0 = blockIdx.x * 128;

    u64 acc[4][4];
    #pragma unroll
    for (int r = 0; r < 4; r++)
        #pragma unroll
        for (int c = 0; c < 4; c++) acc[r][c] = 0ull;

    for (int kb = 0; kb < 192; kb += 16) {
        #pragma unroll
        for (int q = 0; q < 2; q++) {
            int s = tid * 2 + q;
            int row = s >> 2, j = s & 3;
            int gr = m0 + row;
            int k = kb + j * 4;
            float4 v = make_float4(0.f, 0.f, 0.f, 0.f);
            if (gr < N) {
                if (k < 64) v = *(const float4*)(G + (size_t)gr * 64 + k);
                else        v = *(const float4*)(X + (size_t)gr * 128 + (k - 64));
            }
            Xs[j * 4 + 0][row] = v.x; Xs[j * 4 + 1][row] = v.y;
            Xs[j * 4 + 2][row] = v.z; Xs[j * 4 + 3][row] = v.w;
        }
        {
            int k = tid >> 4, c4 = tid & 15;
            int gk = kb + k;
            const float* src = (gk < 64) ? (PW + (size_t)gk * 64 + c4 * 4)
                                         : (RW + (size_t)(gk - 64) * 64 + c4 * 4);
            *(float4*)&Ws[k][c4 * 4] = *(const float4*)src;
        }
        __syncthreads();
        #pragma unroll
        for (int kk = 0; kk < 16; kk++) {
            ulonglong2 aa0 = *(const ulonglong2*)&Xs[kk][tr * 8];
            ulonglong2 aa1 = *(const ulonglong2*)&Xs[kk][tr * 8 + 4];
            float4 b4 = *(const float4*)&Ws[kk][tc * 4];
            u64 d0 = dup2(b4.x), d1 = dup2(b4.y), d2 = dup2(b4.z), d3 = dup2(b4.w);
            u64 a2[4] = { aa0.x, aa0.y, aa1.x, aa1.y };
            #pragma unroll
            for (int r = 0; r < 4; r++) {
                ffma2(acc[r][0], a2[r], d0);
                ffma2(acc[r][1], a2[r], d1);
                ffma2(acc[r][2], a2[r], d2);
                ffma2(acc[r][3], a2[r], d3);
            }
        }
        __syncthreads();
    }

    float4 pb4 = *(const float4*)(pb + tc * 4);
    float4 g4 = *(const float4*)(lg + tc * 4);
    float4 b4 = *(const float4*)(lb + tc * 4);
    float y[8][4];
    #pragma unroll
    for (int r = 0; r < 4; r++)
        #pragma unroll
        for (int c = 0; c < 4; c++) {
            float2 u = unpack2(acc[r][c]);
            y[2 * r][c] = u.x; y[2 * r + 1][c] = u.y;
        }
    #pragma unroll
    for (int r = 0; r < 8; r++) {
        y[r][0] += pb4.x; y[r][1] += pb4.y; y[r][2] += pb4.z; y[r][3] += pb4.w;
        float s1 = y[r][0] + y[r][1] + y[r][2] + y[r][3];
        float s2 = y[r][0] * y[r][0] + y[r][1] * y[r][1] + y[r][2] * y[r][2] + y[r][3] * y[r][3];
        #pragma unroll
        for (int o = 1; o < 16; o <<= 1) {
            s1 += __shfl_xor_sync(0xffffffffu, s1, o);
            s2 += __shfl_xor_sync(0xffffffffu, s2, o);
        }
        float mu = s1 * (1.f / 64.f);
        float var = s2 * (1.f / 64.f) - mu * mu;
        float inv = rsqrtf(var + 1e-5f);
        int row = m0 + tr * 8 + r;
        if (row < N) {
            float4 o4;
            o4.x = (y[r][0] - mu) * inv * g4.x + b4.x;
            o4.y = (y[r][1] - mu) * inv * g4.y + b4.y;
            o4.z = (y[r][2] - mu) * inv * g4.z + b4.z;
            o4.w = (y[r][3] - mu) * inv * g4.w + b4.w;
            *(float4*)(out + (size_t)row * 64 + tc * 4) = o4;
        }
    }
}

// ------------- launch -------------
extern "C" void kernel_launch(void* const* d_in, const int* in_sizes, int n_in,
                              void* d_out, int out_size) {
    const float* x_sku = (const float*)d_in[0];
    const float* x_wh  = (const float*)d_in[1];
    const float* x_sup = (const float*)d_in[2];
    GP6 gp; EP6 ep;
    for (int i = 0; i < 6; i++) {
        gp.W[i] = (const float*)d_in[3 + 2 * i];
        gp.a[i] = (const float*)d_in[4 + 2 * i];
    }
    const float* proj_W = (const float*)d_in[15];
    const float* proj_b = (const float*)d_in[16];
    const float* ln_g   = (const float*)d_in[17];
    const float* ln_b   = (const float*)d_in[18];
    const float* res_W  = (const float*)d_in[19];
    for (int i = 0; i < 6; i++) ep.p[i] = (const int*)d_in[20 + i];
    float* out = (float*)d_out;

    // CSR build
    zero_deg_k<<<(TOTN + 255) / 256, 256>>>();
    count_k<<<dim3((EINTRA + 255) / 256, 6), 256>>>(ep);
    scan_k<<<6, 1024>>>();
    fill_k<<<dim3((EINTRA + 255) / 256, 6), 256>>>(ep);

    // dense phase
    gemm6_k<<<dim3((NSKU + 127) / 128, 6), 256>>>(x_sku, gp);
    dstscore_k<<<NWH, 64>>>(x_wh, gp.W[4], gp.a[4], 0, NWH);
    dstscore_k<<<NSUP, 64>>>(x_sup, gp.W[5], gp.a[5], 1, NSUP);

    // sparse phase
    agg_intra_k<<<(NSKU * 32 + 255) / 256, 256>>>();
    agg_cross_k<<<(NWH * 32 + 255) / 256, 256>>>(4, NWH);
    agg_cross_k<<<(NSUP * 32 + 255) / 256, 256>>>(5, NSUP);

    // finish (output layout: sku block, then wh, then sup)
    finish_k<<<(NSKU + 127) / 128, 256>>>(x_sku, proj_W, res_W, proj_b, ln_g, ln_b,
                                          out, NSKU, 0);
    finish_k<<<(NWH + 127) / 128, 256>>>(x_wh, proj_W + 64 * 64, res_W, proj_b, ln_g, ln_b,
                                         out + (size_t)NSKU * 64, NWH, 1);
    finish_k<<<(NSUP + 127) / 128, 256>>>(x_sup, proj_W + 64 * 64, res_W, proj_b, ln_g, ln_b,
                                          out + (size_t)(NSKU + NWH) * 64, NSUP, 2);
}

// round 5
// speedup vs baseline: 1.1374x; 1.1374x over previous
#include <cuda_runtime.h>
#include <cuda_bf16.h>

#define NSKU 100000
#define NWH  5000
#define NSUP 2000
#define EINTRA 400000
#define ECROSS 200000
#define TOTN (4*NSKU + NWH + NSUP)

typedef unsigned long long u64;

// ------------- static scratch (no allocations allowed) -------------
__device__ float g_H[6 * NSKU * 64];      // transformed sku feats per type
__device__ float g_Ss[6 * NSKU * 4];      // src scores per type/head
__device__ float g_SdI[4 * NSKU * 4];     // dst scores, intra types
__device__ float g_Swh[NWH * 4];
__device__ float g_Ssup[NSUP * 4];
__device__ float g_OA[NSKU * 64];
__device__ float g_OBwh[NWH * 64];
__device__ float g_OBsup[NSUP * 64];
__device__ int g_deg[TOTN];
__device__ int g_cur[TOTN];
__device__ int g_rp[4 * (NSKU + 1) + (NWH + 1) + (NSUP + 1)];
__device__ int g_col[4 * EINTRA + 2 * ECROSS];

// ------------- f32x2 helpers -------------
static __device__ __forceinline__ u64 dup2(float x) {
    u64 r; asm("mov.b64 %0, {%1, %1};" : "=l"(r) : "f"(x)); return r;
}
static __device__ __forceinline__ float2 unpack2(u64 v) {
    float2 d; asm("mov.b64 {%0, %1}, %2;" : "=f"(d.x), "=f"(d.y) : "l"(v)); return d;
}
static __device__ __forceinline__ void ffma2(u64& d, u64 a, u64 b) {
    asm("fma.rn.f32x2 %0, %1, %2, %0;" : "+l"(d) : "l"(a), "l"(b));
}

struct EP6 { const int* p[6]; };
struct GP6 { const float* W[6]; const float* a[6]; };

// ------------- CSR pointer resolver -------------
static __device__ __forceinline__ void csr_ptrs(int t, int& N, int& E,
        int*& deg, int*& rp, int*& cur, int*& col) {
    if (t < 4) {
        N = NSKU; E = EINTRA;
        deg = g_deg + t * NSKU; rp = g_rp + t * (NSKU + 1);
        cur = g_cur + t * NSKU; col = g_col + t * EINTRA;
    } else if (t == 4) {
        N = NWH; E = ECROSS;
        deg = g_deg + 4 * NSKU; rp = g_rp + 4 * (NSKU + 1);
        cur = g_cur + 4 * NSKU; col = g_col + 4 * EINTRA;
    } else {
        N = NSUP; E = ECROSS;
        deg = g_deg + 4 * NSKU + NWH; rp = g_rp + 4 * (NSKU + 1) + (NWH + 1);
        cur = g_cur + 4 * NSKU + NWH; col = g_col + 4 * EINTRA + ECROSS;
    }
}

// ------------- CSR build -------------
__global__ void zero_deg_k() {
    int i = blockIdx.x * 256 + threadIdx.x;
    if (i < TOTN) g_deg[i] = 0;
}

__global__ void count_k(EP6 ep) {
    int t = blockIdx.y;
    int N, E; int *deg, *rp, *cur, *col;
    csr_ptrs(t, N, E, deg, rp, cur, col);
    int e = blockIdx.x * 256 + threadIdx.x;
    if (e >= E) return;
    atomicAdd(&deg[ep.p[t][E + e]], 1);
}

__global__ void __launch_bounds__(1024) scan_k() {
    int t = blockIdx.x;
    int N, E; int *deg, *rp, *cur, *col;
    csr_ptrs(t, N, E, deg, rp, cur, col);
    __shared__ int wsum[32];
    __shared__ int s_carry;
    int tid = threadIdx.x, lane = tid & 31, w = tid >> 5;
    if (tid == 0) s_carry = 0;
    __syncthreads();
    int iters = (N + 1023) >> 10;
    for (int it = 0; it < iters; it++) {
        int i = it * 1024 + tid;
        int v = (i < N) ? deg[i] : 0;
        int x = v;
        #pragma unroll
        for (int o = 1; o < 32; o <<= 1) {
            int y = __shfl_up_sync(0xffffffffu, x, o);
            if (lane >= o) x += y;
        }
        if (lane == 31) wsum[w] = x;
        __syncthreads();
        if (w == 0) {
            int s = wsum[lane];
            #pragma unroll
            for (int o = 1; o < 32; o <<= 1) {
                int y = __shfl_up_sync(0xffffffffu, s, o);
                if (lane >= o) s += y;
            }
            wsum[lane] = s;
        }
        __syncthreads();
        int incl = x + (w > 0 ? wsum[w - 1] : 0) + s_carry;
        int excl = incl - v;
        if (i < N) { rp[i] = excl; cur[i] = excl; }
        __syncthreads();
        if (tid == 1023) s_carry = incl;
        __syncthreads();
    }
    if (tid == 0) rp[N] = s_carry;
}

__global__ void fill_k(EP6 ep) {
    int t = blockIdx.y;
    int N, E; int *deg, *rp, *cur, *col;
    csr_ptrs(t, N, E, deg, rp, cur, col);
    int e = blockIdx.x * 256 + threadIdx.x;
    if (e >= E) return;
    int src = ep.p[t][e];
    int dst = ep.p[t][E + e];
    int pos = atomicAdd(&cur[dst], 1);
    col[pos] = src;
}

// ------------- dense phase: H[t] = x_sku @ W[t], fused score epilogue -------------
__global__ void __launch_bounds__(256) gemm6_k(const float* __restrict__ X, GP6 gp) {
    __shared__ __align__(16) float Xs[16][128];
    __shared__ __align__(16) float Ws[16][64];
    int t = blockIdx.y;
    const float* __restrict__ W = gp.W[t];
    const float* __restrict__ av = gp.a[t];
    int tid = threadIdx.x;
    int tc = tid & 15, tr = tid >> 4;
    int m0 = blockIdx.x * 128;

    u64 acc[4][4];
    #pragma unroll
    for (int r = 0; r < 4; r++)
        #pragma unroll
        for (int c = 0; c < 4; c++) acc[r][c] = 0ull;

    for (int kb = 0; kb < 128; kb += 16) {
        #pragma unroll
        for (int q = 0; q < 2; q++) {
            int s = tid * 2 + q;
            int row = s >> 2, j = s & 3;
            int gr = m0 + row;
            float4 v = make_float4(0.f, 0.f, 0.f, 0.f);
            if (gr < NSKU) v = *(const float4*)(X + (size_t)gr * 128 + kb + j * 4);
            Xs[j * 4 + 0][row] = v.x; Xs[j * 4 + 1][row] = v.y;
            Xs[j * 4 + 2][row] = v.z; Xs[j * 4 + 3][row] = v.w;
        }
        {
            int k = tid >> 4, c4 = tid & 15;
            *(float4*)&Ws[k][c4 * 4] = *(const float4*)(W + (size_t)(kb + k) * 64 + c4 * 4);
        }
        __syncthreads();
        #pragma unroll
        for (int kk = 0; kk < 16; kk++) {
            ulonglong2 aa0 = *(const ulonglong2*)&Xs[kk][tr * 8];
            ulonglong2 aa1 = *(const ulonglong2*)&Xs[kk][tr * 8 + 4];
            float4 b4 = *(const float4*)&Ws[kk][tc * 4];
            u64 d0 = dup2(b4.x), d1 = dup2(b4.y), d2 = dup2(b4.z), d3 = dup2(b4.w);
            u64 a2[4] = { aa0.x, aa0.y, aa1.x, aa1.y };
            #pragma unroll
            for (int r = 0; r < 4; r++) {
                ffma2(acc[r][0], a2[r], d0);
                ffma2(acc[r][1], a2[r], d1);
                ffma2(acc[r][2], a2[r], d2);
                ffma2(acc[r][3], a2[r], d3);
            }
        }
        __syncthreads();
    }

    float out[8][4];
    #pragma unroll
    for (int r = 0; r < 4; r++)
        #pragma unroll
        for (int c = 0; c < 4; c++) {
            float2 u = unpack2(acc[r][c]);
            out[2 * r][c] = u.x; out[2 * r + 1][c] = u.y;
        }

    float4 as4 = *(const float4*)(av + (tc & 3) * 4);
    float4 ad4 = *(const float4*)(av + 16 + (tc & 3) * 4);
    float* Ht = g_H + (size_t)t * NSKU * 64;
    float* Sst = g_Ss + (size_t)t * NSKU * 4;
    float* Sdt = (t < 4) ? (g_SdI + (size_t)t * NSKU * 4) : 0;
    int head = tc >> 2;
    #pragma unroll
    for (int r = 0; r < 8; r++) {
        int row = m0 + tr * 8 + r;
        float ps = out[r][0] * as4.x + out[r][1] * as4.y + out[r][2] * as4.z + out[r][3] * as4.w;
        float pd = out[r][0] * ad4.x + out[r][1] * ad4.y + out[r][2] * ad4.z + out[r][3] * ad4.w;
        ps += __shfl_xor_sync(0xffffffffu, ps, 1);
        ps += __shfl_xor_sync(0xffffffffu, ps, 2);
        pd += __shfl_xor_sync(0xffffffffu, pd, 1);
        pd += __shfl_xor_sync(0xffffffffu, pd, 2);
        if (row < NSKU) {
            *(float4*)(Ht + (size_t)row * 64 + tc * 4) =
                make_float4(out[r][0], out[r][1], out[r][2], out[r][3]);
            if ((tc & 3) == 0) {
                Sst[row * 4 + head] = ps;
                if (Sdt) Sdt[row * 4 + head] = pd;
            }
        }
    }
}

// ------------- dst-side scores for cross types (tiny matvec) -------------
__global__ void dstscore_k(const float* __restrict__ X, const float* __restrict__ W,
                           const float* __restrict__ av, int which, int N) {
    float* S = which ? g_Ssup : g_Swh;
    int n = blockIdx.x;
    if (n >= N) return;
    int d = threadIdx.x;               // 0..63
    const float* xr = X + (size_t)n * 128;
    float h = 0.f;
    for (int k = 0; k < 128; k++) h += xr[k] * W[k * 64 + d];
    float p = h * av[16 + (d & 15)];
    #pragma unroll
    for (int o = 1; o < 16; o <<= 1) p += __shfl_xor_sync(0xffffffffu, p, o);
    if ((d & 15) == 0) S[n * 4 + (d >> 4)] = p;
}

// ------------- edge aggregation: one warp per dst node -------------
__global__ void agg_intra_k() {
    int warp = (blockIdx.x * blockDim.x + threadIdx.x) >> 5;
    int lane = threadIdx.x & 31;
    if (warp >= NSKU) return;
    int dst = warp;
    int head = lane >> 3;
    float2 tot = make_float2(0.f, 0.f);
    #pragma unroll
    for (int t = 0; t < 4; t++) {
        const int* rp = g_rp + t * (NSKU + 1);
        const int* col = g_col + t * EINTRA;
        const float* Ss = g_Ss + (size_t)t * NSKU * 4;
        const float* Sd = g_SdI + (size_t)t * NSKU * 4;
        const float* H = g_H + (size_t)t * NSKU * 64;
        float sd = Sd[dst * 4 + head];
        float2 acc = make_float2(0.f, 0.f);
        float den = 0.f;
        int e1 = rp[dst + 1];
        for (int e = rp[dst]; e < e1; e++) {
            int src = __ldg(&col[e]);
            float x = __ldg(&Ss[src * 4 + head]) + sd;
            float el = x > 0.f ? x : (__expf(x) - 1.f);
            float w = __expf(el);
            float2 h = *(const float2*)(H + (size_t)src * 64 + 2 * lane);
            acc.x += w * h.x; acc.y += w * h.y; den += w;
        }
        float inv = 1.f / (den + 1e-12f);
        tot.x += acc.x * inv; tot.y += acc.y * inv;
    }
    *(float2*)(g_OA + (size_t)dst * 64 + 2 * lane) = tot;
}

__global__ void agg_cross_k(int t, int N) {
    int warp = (blockIdx.x * blockDim.x + threadIdx.x) >> 5;
    int lane = threadIdx.x & 31;
    if (warp >= N) return;
    int dst = warp;
    int head = lane >> 3;
    const int* rp = g_rp + 4 * (NSKU + 1) + (t == 5 ? (NWH + 1) : 0);
    const int* col = g_col + 4 * EINTRA + (t == 5 ? ECROSS : 0);
    const float* Ss = g_Ss + (size_t)t * NSKU * 4;
    const float* Sd = (t == 4) ? g_Swh : g_Ssup;
    const float* H = g_H + (size_t)t * NSKU * 64;
    float* Out = (t == 4) ? g_OBwh : g_OBsup;
    float sd = Sd[dst * 4 + head];
    float2 acc = make_float2(0.f, 0.f);
    float den = 0.f;
    int e1 = rp[dst + 1];
    for (int e = rp[dst]; e < e1; e++) {
        int src = __ldg(&col[e]);
        float x = __ldg(&Ss[src * 4 + head]) + sd;
        float el = x > 0.f ? x : (__expf(x) - 1.f);
        float w = __expf(el);
        float2 h = *(const float2*)(H + (size_t)src * 64 + 2 * lane);
        acc.x += w * h.x; acc.y += w * h.y; den += w;
    }
    float inv = 1.f / (den + 1e-12f);
    *(float2*)(Out + (size_t)dst * 64 + 2 * lane) = make_float2(acc.x * inv, acc.y * inv);
}

// ------------- finish: y = [G|X] @ [PW;RW] + b, LayerNorm -------------
__global__ void __launch_bounds__(256) finish_k(
        const float* __restrict__ X, const float* __restrict__ PW,
        const float* __restrict__ RW, const float* __restrict__ pb,
        const float* __restrict__ lg, const float* __restrict__ lb,
        float* __restrict__ out, int N, int which) {
    const float* __restrict__ G = (which == 0) ? g_OA : (which == 1) ? g_OBwh : g_OBsup;
    __shared__ __align__(16) float Xs[16][128];
    __shared__ __align__(16) float Ws[16][64];
    int tid = threadIdx.x, tc = tid & 15, tr = tid >> 4;
    int m0 = blockIdx.x * 128;

    u64 acc[4][4];
    #pragma unroll
    for (int r = 0; r < 4; r++)
        #pragma unroll
        for (int c = 0; c < 4; c++) acc[r][c] = 0ull;

    for (int kb = 0; kb < 192; kb += 16) {
        #pragma unroll
        for (int q = 0; q < 2; q++) {
            int s = tid * 2 + q;
            int row = s >> 2, j = s & 3;
            int gr = m0 + row;
            int k = kb + j * 4;
            float4 v = make_float4(0.f, 0.f, 0.f, 0.f);
            if (gr < N) {
                if (k < 64) v = *(const float4*)(G + (size_t)gr * 64 + k);
                else        v = *(const float4*)(X + (size_t)gr * 128 + (k - 64));
            }
            Xs[j * 4 + 0][row] = v.x; Xs[j * 4 + 1][row] = v.y;
            Xs[j * 4 + 2][row] = v.z; Xs[j * 4 + 3][row] = v.w;
        }
        {
            int k = tid >> 4, c4 = tid & 15;
            int gk = kb + k;
            const float* src = (gk < 64) ? (PW + (size_t)gk * 64 + c4 * 4)
                                         : (RW + (size_t)(gk - 64) * 64 + c4 * 4);
            *(float4*)&Ws[k][c4 * 4] = *(const float4*)src;
        }
        __syncthreads();
        #pragma unroll
        for (int kk = 0; kk < 16; kk++) {
            ulonglong2 aa0 = *(const ulonglong2*)&Xs[kk][tr * 8];
            ulonglong2 aa1 = *(const ulonglong2*)&Xs[kk][tr * 8 + 4];
            float4 b4 = *(const float4*)&Ws[kk][tc * 4];
            u64 d0 = dup2(b4.x), d1 = dup2(b4.y), d2 = dup2(b4.z), d3 = dup2(b4.w);
            u64 a2[4] = { aa0.x, aa0.y, aa1.x, aa1.y };
            #pragma unroll
            for (int r = 0; r < 4; r++) {
                ffma2(acc[r][0], a2[r], d0);
                ffma2(acc[r][1], a2[r], d1);
                ffma2(acc[r][2], a2[r], d2);
                ffma2(acc[r][3], a2[r], d3);
            }
        }
        __syncthreads();
    }

    float4 pb4 = *(const float4*)(pb + tc * 4);
    float4 g4 = *(const float4*)(lg + tc * 4);
    float4 b4 = *(const float4*)(lb + tc * 4);
    float y[8][4];
    #pragma unroll
    for (int r = 0; r < 4; r++)
        #pragma unroll
        for (int c = 0; c < 4; c++) {
            float2 u = unpack2(acc[r][c]);
            y[2 * r][c] = u.x; y[2 * r + 1][c] = u.y;
        }
    #pragma unroll
    for (int r = 0; r < 8; r++) {
        y[r][0] += pb4.x; y[r][1] += pb4.y; y[r][2] += pb4.z; y[r][3] += pb4.w;
        float s1 = y[r][0] + y[r][1] + y[r][2] + y[r][3];
        float s2 = y[r][0] * y[r][0] + y[r][1] * y[r][1] + y[r][2] * y[r][2] + y[r][3] * y[r][3];
        #pragma unroll
        for (int o = 1; o < 16; o <<= 1) {
            s1 += __shfl_xor_sync(0xffffffffu, s1, o);
            s2 += __shfl_xor_sync(0xffffffffu, s2, o);
        }
        float mu = s1 * (1.f / 64.f);
        float var = s2 * (1.f / 64.f) - mu * mu;
        float inv = rsqrtf(var + 1e-5f);
        int row = m0 + tr * 8 + r;
        if (row < N) {
            float4 o4;
            o4.x = (y[r][0] - mu) * inv * g4.x + b4.x;
            o4.y = (y[r][1] - mu) * inv * g4.y + b4.y;
            o4.z = (y[r][2] - mu) * inv * g4.z + b4.z;
            o4.w = (y[r][3] - mu) * inv * g4.w + b4.w;
            *(float4*)(out + (size_t)row * 64 + tc * 4) = o4;
        }
    }
}

// ------------- launch (3-stream DAG) -------------
extern "C" void kernel_launch(void* const* d_in, const int* in_sizes, int n_in,
                              void* d_out, int out_size) {
    const float* x_sku = (const float*)d_in[0];
    const float* x_wh  = (const float*)d_in[1];
    const float* x_sup = (const float*)d_in[2];
    GP6 gp; EP6 ep;
    for (int i = 0; i < 6; i++) {
        gp.W[i] = (const float*)d_in[3 + 2 * i];
        gp.a[i] = (const float*)d_in[4 + 2 * i];
    }
    const float* proj_W = (const float*)d_in[15];
    const float* proj_b = (const float*)d_in[16];
    const float* ln_g   = (const float*)d_in[17];
    const float* ln_b   = (const float*)d_in[18];
    const float* res_W  = (const float*)d_in[19];
    for (int i = 0; i < 6; i++) ep.p[i] = (const int*)d_in[20 + i];
    float* out = (float*)d_out;

    // one-time side streams + events (host objects only; created on the
    // non-captured correctness call, reused identically every call)
    static cudaStream_t s1 = 0, s2 = 0;
    static cudaEvent_t ev_root = 0, ev_csr = 0, ev_gemm = 0, ev_s2 = 0;
    if (!s1) {
        cudaStreamCreateWithFlags(&s1, cudaStreamNonBlocking);
        cudaStreamCreateWithFlags(&s2, cudaStreamNonBlocking);
        cudaEventCreateWithFlags(&ev_root, cudaEventDisableTiming);
        cudaEventCreateWithFlags(&ev_csr, cudaEventDisableTiming);
        cudaEventCreateWithFlags(&ev_gemm, cudaEventDisableTiming);
        cudaEventCreateWithFlags(&ev_s2, cudaEventDisableTiming);
    }

    // fork
    cudaEventRecord(ev_root, 0);
    cudaStreamWaitEvent(s1, ev_root, 0);
    cudaStreamWaitEvent(s2, ev_root, 0);

    // S1: CSR build
    zero_deg_k<<<(TOTN + 255) / 256, 256, 0, s1>>>();
    count_k<<<dim3((EINTRA + 255) / 256, 6), 256, 0, s1>>>(ep);
    scan_k<<<6, 1024, 0, s1>>>();
    fill_k<<<dim3((EINTRA + 255) / 256, 6), 256, 0, s1>>>(ep);
    cudaEventRecord(ev_csr, s1);

    // S2: dst-side scores for cross types
    dstscore_k<<<NWH, 64, 0, s2>>>(x_wh, gp.W[4], gp.a[4], 0, NWH);
    dstscore_k<<<NSUP, 64, 0, s2>>>(x_sup, gp.W[5], gp.a[5], 1, NSUP);

    // S0: dense phase (critical path)
    gemm6_k<<<dim3((NSKU + 127) / 128, 6), 256>>>(x_sku, gp);
    cudaEventRecord(ev_gemm, 0);

    // S0: sku chain
    cudaStreamWaitEvent(0, ev_csr, 0);
    agg_intra_k<<<(NSKU * 32 + 255) / 256, 256>>>();
    finish_k<<<(NSKU + 127) / 128, 256>>>(x_sku, proj_W, res_W, proj_b, ln_g, ln_b,
                                          out, NSKU, 0);

    // S2: cross chains
    cudaStreamWaitEvent(s2, ev_gemm, 0);
    cudaStreamWaitEvent(s2, ev_csr, 0);
    agg_cross_k<<<(NWH * 32 + 255) / 256, 256, 0, s2>>>(4, NWH);
    agg_cross_k<<<(NSUP * 32 + 255) / 256, 256, 0, s2>>>(5, NSUP);
    finish_k<<<(NWH + 127) / 128, 256, 0, s2>>>(x_wh, proj_W + 64 * 64, res_W, proj_b,
                                                ln_g, ln_b, out + (size_t)NSKU * 64, NWH, 1);
    finish_k<<<(NSUP + 127) / 128, 256, 0, s2>>>(x_sup, proj_W + 64 * 64, res_W, proj_b,
                                                 ln_g, ln_b, out + (size_t)(NSKU + NWH) * 64,
                                                 NSUP, 2);
    cudaEventRecord(ev_s2, s2);

    // join everything back onto the capture stream
    cudaStreamWaitEvent(0, ev_s2, 0);
}

// round 7
// speedup vs baseline: 1.1779x; 1.0356x over previous
#include <cuda_runtime.h>
#include <cuda_bf16.h>

#define NSKU 100000
#define NWH  5000
#define NSUP 2000
#define EINTRA 400000
#define ECROSS 200000
#define TOTN (4*NSKU + NWH + NSUP)

typedef unsigned long long u64;
typedef unsigned int u32;

// ------------- static scratch (no allocations allowed) -------------
__device__ float g_H[6 * NSKU * 64];      // transformed sku feats per type
__device__ float g_Ss[6 * NSKU * 4];      // src scores per type/head
__device__ float g_SdI[4 * NSKU * 4];     // dst scores, intra types
__device__ float g_Swh[NWH * 4];
__device__ float g_Ssup[NSUP * 4];
__device__ float g_OA[NSKU * 64];
__device__ float g_OBwh[NWH * 64];
__device__ float g_OBsup[NSUP * 64];
__device__ int g_deg[TOTN];
__device__ int g_cur[TOTN];
__device__ int g_rp[4 * (NSKU + 1) + (NWH + 1) + (NSUP + 1)];
__device__ int g_col[4 * EINTRA + 2 * ECROSS];

// ------------- f32x2 helpers (finish_k) -------------
static __device__ __forceinline__ u64 dup2(float x) {
    u64 r; asm("mov.b64 %0, {%1, %1};" : "=l"(r) : "f"(x)); return r;
}
static __device__ __forceinline__ float2 unpack2(u64 v) {
    float2 d; asm("mov.b64 {%0, %1}, %2;" : "=f"(d.x), "=f"(d.y) : "l"(v)); return d;
}
static __device__ __forceinline__ void ffma2(u64& d, u64 a, u64 b) {
    asm("fma.rn.f32x2 %0, %1, %2, %0;" : "+l"(d) : "l"(a), "l"(b));
}

// ------------- tf32 helpers -------------
static __device__ __forceinline__ float to_tf32(float x) {
    u32 u; asm("cvt.rna.tf32.f32 %0, %1;" : "=r"(u) : "f"(x));
    return __uint_as_float(u);
}
static __device__ __forceinline__ void cvt4(float4& v) {
    v.x = to_tf32(v.x); v.y = to_tf32(v.y); v.z = to_tf32(v.z); v.w = to_tf32(v.w);
}
static __device__ __forceinline__ void mma_tf32(float* d, u32 a0, u32 a1, u32 a2, u32 a3,
                                                u32 b0, u32 b1) {
    asm volatile("mma.sync.aligned.m16n8k8.row.col.f32.tf32.tf32.f32 "
                 "{%0,%1,%2,%3}, {%4,%5,%6,%7}, {%8,%9}, {%0,%1,%2,%3};"
                 : "+f"(d[0]), "+f"(d[1]), "+f"(d[2]), "+f"(d[3])
                 : "r"(a0), "r"(a1), "r"(a2), "r"(a3), "r"(b0), "r"(b1));
}

struct EP6 { const int* p[6]; };
struct GP6 { const float* W[6]; const float* a[6]; };

// ------------- CSR pointer resolver -------------
static __device__ __forceinline__ void csr_ptrs(int t, int& N, int& E,
        int*& deg, int*& rp, int*& cur, int*& col) {
    if (t < 4) {
        N = NSKU; E = EINTRA;
        deg = g_deg + t * NSKU; rp = g_rp + t * (NSKU + 1);
        cur = g_cur + t * NSKU; col = g_col + t * EINTRA;
    } else if (t == 4) {
        N = NWH; E = ECROSS;
        deg = g_deg + 4 * NSKU; rp = g_rp + 4 * (NSKU + 1);
        cur = g_cur + 4 * NSKU; col = g_col + 4 * EINTRA;
    } else {
        N = NSUP; E = ECROSS;
        deg = g_deg + 4 * NSKU + NWH; rp = g_rp + 4 * (NSKU + 1) + (NWH + 1);
        cur = g_cur + 4 * NSKU + NWH; col = g_col + 4 * EINTRA + ECROSS;
    }
}

// ------------- CSR build -------------
__global__ void zero_deg_k() {
    int i = blockIdx.x * 256 + threadIdx.x;
    if (i < TOTN) g_deg[i] = 0;
}

// 4 edges per thread, int4 loads -> MLP=4 on the atomic chains
__global__ void count_k(EP6 ep) {
    int t = blockIdx.y;
    int N, E; int *deg, *rp, *cur, *col;
    csr_ptrs(t, N, E, deg, rp, cur, col);
    int base = (blockIdx.x * 256 + threadIdx.x) * 4;
    if (base >= E) return;
    int4 d4 = *(const int4*)(ep.p[t] + E + base);   // E % 4 == 0 for all types
    atomicAdd(&deg[d4.x], 1);
    atomicAdd(&deg[d4.y], 1);
    atomicAdd(&deg[d4.z], 1);
    atomicAdd(&deg[d4.w], 1);
}

__global__ void __launch_bounds__(1024) scan_k() {
    int t = blockIdx.x;
    int N, E; int *deg, *rp, *cur, *col;
    csr_ptrs(t, N, E, deg, rp, cur, col);
    __shared__ int wsum[32];
    __shared__ int s_carry;
    int tid = threadIdx.x, lane = tid & 31, w = tid >> 5;
    if (tid == 0) s_carry = 0;
    __syncthreads();
    int iters = (N + 1023) >> 10;
    for (int it = 0; it < iters; it++) {
        int i = it * 1024 + tid;
        int v = (i < N) ? deg[i] : 0;
        int x = v;
        #pragma unroll
        for (int o = 1; o < 32; o <<= 1) {
            int y = __shfl_up_sync(0xffffffffu, x, o);
            if (lane >= o) x += y;
        }
        if (lane == 31) wsum[w] = x;
        __syncthreads();
        if (w == 0) {
            int s = wsum[lane];
            #pragma unroll
            for (int o = 1; o < 32; o <<= 1) {
                int y = __shfl_up_sync(0xffffffffu, s, o);
                if (lane >= o) s += y;
            }
            wsum[lane] = s;
        }
        __syncthreads();
        int incl = x + (w > 0 ? wsum[w - 1] : 0) + s_carry;
        int excl = incl - v;
        if (i < N) { rp[i] = excl; cur[i] = excl; }
        __syncthreads();
        if (tid == 1023) s_carry = incl;
        __syncthreads();
    }
    if (tid == 0) rp[N] = s_carry;
}

__global__ void fill_k(EP6 ep) {
    int t = blockIdx.y;
    int N, E; int *deg, *rp, *cur, *col;
    csr_ptrs(t, N, E, deg, rp, cur, col);
    int base = (blockIdx.x * 256 + threadIdx.x) * 4;
    if (base >= E) return;
    int4 s4 = *(const int4*)(ep.p[t] + base);
    int4 d4 = *(const int4*)(ep.p[t] + E + base);
    int p0 = atomicAdd(&cur[d4.x], 1);
    int p1 = atomicAdd(&cur[d4.y], 1);
    int p2 = atomicAdd(&cur[d4.z], 1);
    int p3 = atomicAdd(&cur[d4.w], 1);
    col[p0] = s4.x; col[p1] = s4.y; col[p2] = s4.z; col[p3] = s4.w;
}

// ------------- dense phase: H[t] = x_sku @ W[t] via tf32 mma, fused scores -------------
// BM=128, BN=64, 8 warps; warp w owns rows [16w,16w+16); k permutation inside the
// fragment (kpos t -> 2t, t+4 -> 2t+1) makes all fragment loads contiguous LDS.64.
__global__ void __launch_bounds__(256) gemm6_k(const float* __restrict__ X, GP6 gp) {
    __shared__ __align__(16) float Xs[128][36];
    __shared__ __align__(16) float WsT[64][36];
    int t = blockIdx.y;
    const float* __restrict__ W = gp.W[t];
    const float* __restrict__ av = gp.a[t];
    int tid = threadIdx.x;
    int wid = tid >> 5, lane = tid & 31;
    int g = lane >> 2, tg = lane & 3;
    int m0 = blockIdx.x * 128;
    int mw = wid * 16;

    float acc[8][4];
    #pragma unroll
    for (int j = 0; j < 8; j++)
        #pragma unroll
        for (int c = 0; c < 4; c++) acc[j][c] = 0.f;

    for (int kb = 0; kb < 128; kb += 32) {
        // stage X tile [128 rows][32 k], row-major, tf32-rounded
        #pragma unroll
        for (int q = 0; q < 4; q++) {
            int f = tid + q * 256;
            int row = f >> 3, c4 = (f & 7) * 4;
            int gr = m0 + row;
            float4 v = make_float4(0.f, 0.f, 0.f, 0.f);
            if (gr < NSKU) v = *(const float4*)(X + (size_t)gr * 128 + kb + c4);
            cvt4(v);
            *(float4*)&Xs[row][c4] = v;
        }
        // stage W transposed [64 n][32 k], tf32-rounded
        #pragma unroll
        for (int q = 0; q < 2; q++) {
            int f = tid + q * 256;
            int k = f >> 4, n4 = (f & 15) * 4;
            float4 v = *(const float4*)(W + (size_t)(kb + k) * 64 + n4);
            cvt4(v);
            WsT[n4 + 0][k] = v.x; WsT[n4 + 1][k] = v.y;
            WsT[n4 + 2][k] = v.z; WsT[n4 + 3][k] = v.w;
        }
        __syncthreads();
        #pragma unroll
        for (int ks = 0; ks < 4; ks++) {
            int k0 = ks * 8 + 2 * tg;
            float2 a02 = *(const float2*)&Xs[mw + g][k0];
            float2 a13 = *(const float2*)&Xs[mw + g + 8][k0];
            u32 a0 = __float_as_uint(a02.x), a1 = __float_as_uint(a13.x);
            u32 a2 = __float_as_uint(a02.y), a3 = __float_as_uint(a13.y);
            #pragma unroll
            for (int j = 0; j < 8; j++) {
                float2 b01 = *(const float2*)&WsT[8 * j + g][k0];
                mma_tf32(acc[j], a0, a1, a2, a3,
                         __float_as_uint(b01.x), __float_as_uint(b01.y));
            }
        }
        __syncthreads();
    }

    // epilogue: H store + per-head score dots
    int r0 = m0 + mw + g;
    int r1 = r0 + 8;
    float* Ht = g_H + (size_t)t * NSKU * 64;
    float* Sst = g_Ss + (size_t)t * NSKU * 4;
    float* Sdt = (t < 4) ? (g_SdI + (size_t)t * NSKU * 4) : 0;

    #pragma unroll
    for (int j = 0; j < 8; j++) {
        int c = 8 * j + 2 * tg;
        if (r0 < NSKU) *(float2*)(Ht + (size_t)r0 * 64 + c) = make_float2(acc[j][0], acc[j][1]);
        if (r1 < NSKU) *(float2*)(Ht + (size_t)r1 * 64 + c) = make_float2(acc[j][2], acc[j][3]);
    }

    float2 sA0 = *(const float2*)(av + 2 * tg);
    float2 sA1 = *(const float2*)(av + 8 + 2 * tg);
    float2 dA0 = *(const float2*)(av + 16 + 2 * tg);
    float2 dA1 = *(const float2*)(av + 24 + 2 * tg);
    #pragma unroll
    for (int h = 0; h < 4; h++) {
        float p0 = acc[2*h][0] * sA0.x + acc[2*h][1] * sA0.y
                 + acc[2*h+1][0] * sA1.x + acc[2*h+1][1] * sA1.y;
        float p1 = acc[2*h][2] * sA0.x + acc[2*h][3] * sA0.y
                 + acc[2*h+1][2] * sA1.x + acc[2*h+1][3] * sA1.y;
        float q0 = acc[2*h][0] * dA0.x + acc[2*h][1] * dA0.y
                 + acc[2*h+1][0] * dA1.x + acc[2*h+1][1] * dA1.y;
        float q1 = acc[2*h][2] * dA0.x + acc[2*h][3] * dA0.y
                 + acc[2*h+1][2] * dA1.x + acc[2*h+1][3] * dA1.y;
        #pragma unroll
        for (int o = 1; o < 4; o <<= 1) {
            p0 += __shfl_xor_sync(0xffffffffu, p0, o);
            p1 += __shfl_xor_sync(0xffffffffu, p1, o);
            q0 += __shfl_xor_sync(0xffffffffu, q0, o);
            q1 += __shfl_xor_sync(0xffffffffu, q1, o);
        }
        if (tg == 0) {
            if (r0 < NSKU) { Sst[r0 * 4 + h] = p0; if (Sdt) Sdt[r0 * 4 + h] = q0; }
            if (r1 < NSKU) { Sst[r1 * 4 + h] = p1; if (Sdt) Sdt[r1 * 4 + h] = q1; }
        }
    }
}

// ------------- dst-side scores for cross types (tiny matvec) -------------
__global__ void dstscore_k(const float* __restrict__ X, const float* __restrict__ W,
                           const float* __restrict__ av, int which, int N) {
    float* S = which ? g_Ssup : g_Swh;
    int n = blockIdx.x;
    if (n >= N) return;
    int d = threadIdx.x;               // 0..63
    const float* xr = X + (size_t)n * 128;
    float h = 0.f;
    for (int k = 0; k < 128; k++) h += xr[k] * W[k * 64 + d];
    float p = h * av[16 + (d & 15)];
    #pragma unroll
    for (int o = 1; o < 16; o <<= 1) p += __shfl_xor_sync(0xffffffffu, p, o);
    if ((d & 15) == 0) S[n * 4 + (d >> 4)] = p;
}

// ------------- edge aggregation: one warp per dst node -------------
__global__ void agg_intra_k() {
    int warp = (blockIdx.x * blockDim.x + threadIdx.x) >> 5;
    int lane = threadIdx.x & 31;
    if (warp >= NSKU) return;
    int dst = warp;
    int head = lane >> 3;
    float2 tot = make_float2(0.f, 0.f);
    #pragma unroll
    for (int t = 0; t < 4; t++) {
        const int* rp = g_rp + t * (NSKU + 1);
        const int* col = g_col + t * EINTRA;
        const float* Ss = g_Ss + (size_t)t * NSKU * 4;
        const float* Sd = g_SdI + (size_t)t * NSKU * 4;
        const float* H = g_H + (size_t)t * NSKU * 64;
        float sd = Sd[dst * 4 + head];
        float2 acc = make_float2(0.f, 0.f);
        float den = 0.f;
        int e1 = rp[dst + 1];
        for (int e = rp[dst]; e < e1; e++) {
            int src = __ldg(&col[e]);
            float x = __ldg(&Ss[src * 4 + head]) + sd;
            float el = x > 0.f ? x : (__expf(x) - 1.f);
            float w = __expf(el);
            float2 h = *(const float2*)(H + (size_t)src * 64 + 2 * lane);
            acc.x += w * h.x; acc.y += w * h.y; den += w;
        }
        float inv = 1.f / (den + 1e-12f);
        tot.x += acc.x * inv; tot.y += acc.y * inv;
    }
    *(float2*)(g_OA + (size_t)dst * 64 + 2 * lane) = tot;
}

__global__ void agg_cross_k(int t, int N) {
    int warp = (blockIdx.x * blockDim.x + threadIdx.x) >> 5;
    int lane = threadIdx.x & 31;
    if (warp >= N) return;
    int dst = warp;
    int head = lane >> 3;
    const int* rp = g_rp + 4 * (NSKU + 1) + (t == 5 ? (NWH + 1) : 0);
    const int* col = g_col + 4 * EINTRA + (t == 5 ? ECROSS : 0);
    const float* Ss = g_Ss + (size_t)t * NSKU * 4;
    const float* Sd = (t == 4) ? g_Swh : g_Ssup;
    const float* H = g_H + (size_t)t * NSKU * 64;
    float* Out = (t == 4) ? g_OBwh : g_OBsup;
    float sd = Sd[dst * 4 + head];
    float2 acc = make_float2(0.f, 0.f);
    float den = 0.f;
    int e1 = rp[dst + 1];
    for (int e = rp[dst]; e < e1; e++) {
        int src = __ldg(&col[e]);
        float x = __ldg(&Ss[src * 4 + head]) + sd;
        float el = x > 0.f ? x : (__expf(x) - 1.f);
        float w = __expf(el);
        float2 h = *(const float2*)(H + (size_t)src * 64 + 2 * lane);
        acc.x += w * h.x; acc.y += w * h.y; den += w;
    }
    float inv = 1.f / (den + 1e-12f);
    *(float2*)(Out + (size_t)dst * 64 + 2 * lane) = make_float2(acc.x * inv, acc.y * inv);
}

// ------------- finish: y = [G|X] @ [PW;RW] + b, LayerNorm (fp32 FFMA2) -------------
__global__ void __launch_bounds__(256) finish_k(
        const float* __restrict__ X, const float* __restrict__ PW,
        const float* __restrict__ RW, const float* __restrict__ pb,
        const float* __restrict__ lg, const float* __restrict__ lb,
        float* __restrict__ out, int N, int which) {
    const float* __restrict__ G = (which == 0) ? g_OA : (which == 1) ? g_OBwh : g_OBsup;
    __shared__ __align__(16) float Xs[16][128];
    __shared__ __align__(16) float Ws[16][64];
    int tid = threadIdx.x, tc = tid & 15, tr = tid >> 4;
    int m0 = blockIdx.x * 128;

    u64 acc[4][4];
    #pragma unroll
    for (int r = 0; r < 4; r++)
        #pragma unroll
        for (int c = 0; c < 4; c++) acc[r][c] = 0ull;

    for (int kb = 0; kb < 192; kb += 16) {
        #pragma unroll
        for (int q = 0; q < 2; q++) {
            int s = tid * 2 + q;
            int row = s >> 2, j = s & 3;
            int gr = m0 + row;
            int k = kb + j * 4;
            float4 v = make_float4(0.f, 0.f, 0.f, 0.f);
            if (gr < N) {
                if (k < 64) v = *(const float4*)(G + (size_t)gr * 64 + k);
                else        v = *(const float4*)(X + (size_t)gr * 128 + (k - 64));
            }
            Xs[j * 4 + 0][row] = v.x; Xs[j * 4 + 1][row] = v.y;
            Xs[j * 4 + 2][row] = v.z; Xs[j * 4 + 3][row] = v.w;
        }
        {
            int k = tid >> 4, c4 = tid & 15;
            int gk = kb + k;
            const float* src = (gk < 64) ? (PW + (size_t)gk * 64 + c4 * 4)
                                         : (RW + (size_t)(gk - 64) * 64 + c4 * 4);
            *(float4*)&Ws[k][c4 * 4] = *(const float4*)src;
        }
        __syncthreads();
        #pragma unroll
        for (int kk = 0; kk < 16; kk++) {
            ulonglong2 aa0 = *(const ulonglong2*)&Xs[kk][tr * 8];
            ulonglong2 aa1 = *(const ulonglong2*)&Xs[kk][tr * 8 + 4];
            float4 b4 = *(const float4*)&Ws[kk][tc * 4];
            u64 d0 = dup2(b4.x), d1 = dup2(b4.y), d2 = dup2(b4.z), d3 = dup2(b4.w);
            u64 a2[4] = { aa0.x, aa0.y, aa1.x, aa1.y };
            #pragma unroll
            for (int r = 0; r < 4; r++) {
                ffma2(acc[r][0], a2[r], d0);
                ffma2(acc[r][1], a2[r], d1);
                ffma2(acc[r][2], a2[r], d2);
                ffma2(acc[r][3], a2[r], d3);
            }
        }
        __syncthreads();
    }

    float4 pb4 = *(const float4*)(pb + tc * 4);
    float4 g4 = *(const float4*)(lg + tc * 4);
    float4 b4 = *(const float4*)(lb + tc * 4);
    float y[8][4];
    #pragma unroll
    for (int r = 0; r < 4; r++)
        #pragma unroll
        for (int c = 0; c < 4; c++) {
            float2 u = unpack2(acc[r][c]);
            y[2 * r][c] = u.x; y[2 * r + 1][c] = u.y;
        }
    #pragma unroll
    for (int r = 0; r < 8; r++) {
        y[r][0] += pb4.x; y[r][1] += pb4.y; y[r][2] += pb4.z; y[r][3] += pb4.w;
        float s1 = y[r][0] + y[r][1] + y[r][2] + y[r][3];
        float s2 = y[r][0] * y[r][0] + y[r][1] * y[r][1] + y[r][2] * y[r][2] + y[r][3] * y[r][3];
        #pragma unroll
        for (int o = 1; o < 16; o <<= 1) {
            s1 += __shfl_xor_sync(0xffffffffu, s1, o);
            s2 += __shfl_xor_sync(0xffffffffu, s2, o);
        }
        float mu = s1 * (1.f / 64.f);
        float var = s2 * (1.f / 64.f) - mu * mu;
        float inv = rsqrtf(var + 1e-5f);
        int row = m0 + tr * 8 + r;
        if (row < N) {
            float4 o4;
            o4.x = (y[r][0] - mu) * inv * g4.x + b4.x;
            o4.y = (y[r][1] - mu) * inv * g4.y + b4.y;
            o4.z = (y[r][2] - mu) * inv * g4.z + b4.z;
            o4.w = (y[r][3] - mu) * inv * g4.w + b4.w;
            *(float4*)(out + (size_t)row * 64 + tc * 4) = o4;
        }
    }
}

// ------------- launch (3-stream DAG) -------------
extern "C" void kernel_launch(void* const* d_in, const int* in_sizes, int n_in,
                              void* d_out, int out_size) {
    const float* x_sku = (const float*)d_in[0];
    const float* x_wh  = (const float*)d_in[1];
    const float* x_sup = (const float*)d_in[2];
    GP6 gp; EP6 ep;
    for (int i = 0; i < 6; i++) {
        gp.W[i] = (const float*)d_in[3 + 2 * i];
        gp.a[i] = (const float*)d_in[4 + 2 * i];
    }
    const float* proj_W = (const float*)d_in[15];
    const float* proj_b = (const float*)d_in[16];
    const float* ln_g   = (const float*)d_in[17];
    const float* ln_b   = (const float*)d_in[18];
    const float* res_W  = (const float*)d_in[19];
    for (int i = 0; i < 6; i++) ep.p[i] = (const int*)d_in[20 + i];
    float* out = (float*)d_out;

    static cudaStream_t s1 = 0, s2 = 0;
    static cudaEvent_t ev_root = 0, ev_csr = 0, ev_gemm = 0, ev_s2 = 0;
    if (!s1) {
        cudaStreamCreateWithFlags(&s1, cudaStreamNonBlocking);
        cudaStreamCreateWithFlags(&s2, cudaStreamNonBlocking);
        cudaEventCreateWithFlags(&ev_root, cudaEventDisableTiming);
        cudaEventCreateWithFlags(&ev_csr, cudaEventDisableTiming);
        cudaEventCreateWithFlags(&ev_gemm, cudaEventDisableTiming);
        cudaEventCreateWithFlags(&ev_s2, cudaEventDisableTiming);
    }

    // fork
    cudaEventRecord(ev_root, 0);
    cudaStreamWaitEvent(s1, ev_root, 0);
    cudaStreamWaitEvent(s2, ev_root, 0);

    // S1: CSR build (4 edges per thread in count/fill)
    zero_deg_k<<<(TOTN + 255) / 256, 256, 0, s1>>>();
    count_k<<<dim3((EINTRA / 4 + 255) / 256, 6), 256, 0, s1>>>(ep);
    scan_k<<<6, 1024, 0, s1>>>();
    fill_k<<<dim3((EINTRA / 4 + 255) / 256, 6), 256, 0, s1>>>(ep);
    cudaEventRecord(ev_csr, s1);

    // S2: dst-side scores for cross types
    dstscore_k<<<NWH, 64, 0, s2>>>(x_wh, gp.W[4], gp.a[4], 0, NWH);
    dstscore_k<<<NSUP, 64, 0, s2>>>(x_sup, gp.W[5], gp.a[5], 1, NSUP);

    // S0: dense phase (tf32 tensor cores)
    gemm6_k<<<dim3((NSKU + 127) / 128, 6), 256>>>(x_sku, gp);
    cudaEventRecord(ev_gemm, 0);

    // S0: sku chain
    cudaStreamWaitEvent(0, ev_csr, 0);
    agg_intra_k<<<(NSKU * 32 + 255) / 256, 256>>>();
    finish_k<<<(NSKU + 127) / 128, 256>>>(x_sku, proj_W, res_W, proj_b, ln_g, ln_b,
                                          out, NSKU, 0);

    // S2: cross chains
    cudaStreamWaitEvent(s2, ev_gemm, 0);
    cudaStreamWaitEvent(s2, ev_csr, 0);
    agg_cross_k<<<(NWH * 32 + 255) / 256, 256, 0, s2>>>(4, NWH);
    agg_cross_k<<<(NSUP * 32 + 255) / 256, 256, 0, s2>>>(5, NSUP);
    finish_k<<<(NWH + 127) / 128, 256, 0, s2>>>(x_wh, proj_W + 64 * 64, res_W, proj_b,
                                                ln_g, ln_b, out + (size_t)NSKU * 64, NWH, 1);
    finish_k<<<(NSUP + 127) / 128, 256, 0, s2>>>(x_sup, proj_W + 64 * 64, res_W, proj_b,
                                                 ln_g, ln_b, out + (size_t)(NSKU + NWH) * 64,
                                                 NSUP, 2);
    cudaEventRecord(ev_s2, s2);

    // join
    cudaStreamWaitEvent(0, ev_s2, 0);
}

// round 9
// speedup vs baseline: 1.4519x; 1.2326x over previous
#include <cuda_runtime.h>
#include <cuda_bf16.h>
#include <cuda_fp16.h>

#define NSKU 100000
#define NWH  5000
#define NSUP 2000
#define EINTRA 400000
#define ECROSS 200000
#define TOTN (4*NSKU + NWH + NSUP)
#define SCB 98   // max 1024-blocks per type for scan

typedef unsigned long long u64;
typedef unsigned int u32;

// ------------- static scratch (no allocations allowed) -------------
__device__ __half g_Hh[6 * NSKU * 64];    // transformed sku feats per type (fp16)
__device__ float g_Ss[6 * NSKU * 4];      // src scores per type/head (fp32)
__device__ float g_SdI[4 * NSKU * 4];     // dst scores, intra types
__device__ float g_Swh[NWH * 4];
__device__ float g_Ssup[NSUP * 4];
__device__ float g_OA[NSKU * 64];
__device__ float g_OBwh[NWH * 64];
__device__ float g_OBsup[NSUP * 64];
__device__ int g_deg[TOTN];
__device__ int g_cur[TOTN];
__device__ int g_rp[4 * (NSKU + 1) + (NWH + 1) + (NSUP + 1)];
__device__ int g_col[4 * EINTRA + 2 * ECROSS];
__device__ int g_bs[6 * SCB];

// ------------- tf32 helpers -------------
static __device__ __forceinline__ float to_tf32(float x) {
    u32 u; asm("cvt.rna.tf32.f32 %0, %1;" : "=r"(u) : "f"(x));
    return __uint_as_float(u);
}
static __device__ __forceinline__ void cvt4(float4& v) {
    v.x = to_tf32(v.x); v.y = to_tf32(v.y); v.z = to_tf32(v.z); v.w = to_tf32(v.w);
}
static __device__ __forceinline__ void mma_tf32(float* d, u32 a0, u32 a1, u32 a2, u32 a3,
                                                u32 b0, u32 b1) {
    asm volatile("mma.sync.aligned.m16n8k8.row.col.f32.tf32.tf32.f32 "
                 "{%0,%1,%2,%3}, {%4,%5,%6,%7}, {%8,%9}, {%0,%1,%2,%3};"
                 : "+f"(d[0]), "+f"(d[1]), "+f"(d[2]), "+f"(d[3])
                 : "r"(a0), "r"(a1), "r"(a2), "r"(a3), "r"(b0), "r"(b1));
}

struct EP6 { const int* p[6]; };
struct GP6 { const float* W[6]; const float* a[6]; };

// ------------- CSR pointer resolver -------------
static __device__ __forceinline__ void csr_ptrs(int t, int& N, int& E,
        int*& deg, int*& rp, int*& cur, int*& col) {
    if (t < 4) {
        N = NSKU; E = EINTRA;
        deg = g_deg + t * NSKU; rp = g_rp + t * (NSKU + 1);
        cur = g_cur + t * NSKU; col = g_col + t * EINTRA;
    } else if (t == 4) {
        N = NWH; E = ECROSS;
        deg = g_deg + 4 * NSKU; rp = g_rp + 4 * (NSKU + 1);
        cur = g_cur + 4 * NSKU; col = g_col + 4 * EINTRA;
    } else {
        N = NSUP; E = ECROSS;
        deg = g_deg + 4 * NSKU + NWH; rp = g_rp + 4 * (NSKU + 1) + (NWH + 1);
        cur = g_cur + 4 * NSKU + NWH; col = g_col + 4 * EINTRA + ECROSS;
    }
}

// ------------- CSR build -------------
__global__ void zero_deg_k() {
    int i = blockIdx.x * 256 + threadIdx.x;
    if (i < TOTN) g_deg[i] = 0;
}

__global__ void count_k(EP6 ep) {
    int t = blockIdx.y;
    int N, E; int *deg, *rp, *cur, *col;
    csr_ptrs(t, N, E, deg, rp, cur, col);
    int base = (blockIdx.x * 256 + threadIdx.x) * 4;
    if (base >= E) return;
    int4 d4 = *(const int4*)(ep.p[t] + E + base);
    atomicAdd(&deg[d4.x], 1);
    atomicAdd(&deg[d4.y], 1);
    atomicAdd(&deg[d4.z], 1);
    atomicAdd(&deg[d4.w], 1);
}

// block-local inclusive scan; rp[i] = local-exclusive; block total -> g_bs
__global__ void __launch_bounds__(1024) scanA_k() {
    int t = blockIdx.y;
    int N, E; int *deg, *rp, *cur, *col;
    csr_ptrs(t, N, E, deg, rp, cur, col);
    int nb = (N + 1023) >> 10;
    if ((int)blockIdx.x >= nb) return;
    __shared__ int wsum[32];
    int tid = threadIdx.x, lane = tid & 31, w = tid >> 5;
    int i = blockIdx.x * 1024 + tid;
    int v = (i < N) ? deg[i] : 0;
    int x = v;
    #pragma unroll
    for (int o = 1; o < 32; o <<= 1) {
        int y = __shfl_up_sync(0xffffffffu, x, o);
        if (lane >= o) x += y;
    }
    if (lane == 31) wsum[w] = x;
    __syncthreads();
    if (w == 0) {
        int s = wsum[lane];
        #pragma unroll
        for (int o = 1; o < 32; o <<= 1) {
            int y = __shfl_up_sync(0xffffffffu, s, o);
            if (lane >= o) s += y;
        }
        wsum[lane] = s;
    }
    __syncthreads();
    int incl = x + (w > 0 ? wsum[w - 1] : 0);
    if (i < N) rp[i] = incl - v;
    if (tid == 1023) g_bs[t * SCB + blockIdx.x] = incl;
}

// scan of block sums; writes rp[N]
__global__ void __launch_bounds__(128) scanB_k() {
    int t = blockIdx.x;
    int N, E; int *deg, *rp, *cur, *col;
    csr_ptrs(t, N, E, deg, rp, cur, col);
    int nb = (N + 1023) >> 10;
    __shared__ int wsum[4];
    int tid = threadIdx.x, lane = tid & 31, w = tid >> 5;
    int v = (tid < nb) ? g_bs[t * SCB + tid] : 0;
    int x = v;
    #pragma unroll
    for (int o = 1; o < 32; o <<= 1) {
        int y = __shfl_up_sync(0xffffffffu, x, o);
        if (lane >= o) x += y;
    }
    if (lane == 31) wsum[w] = x;
    __syncthreads();
    if (tid == 0) {
        int run = 0;
        #pragma unroll
        for (int j = 0; j < 4; j++) { int s = wsum[j]; wsum[j] = run; run += s; }
    }
    __syncthreads();
    int incl = x + wsum[w];
    if (tid < nb) g_bs[t * SCB + tid] = incl - v;   // exclusive block offset
    if (tid == 127) rp[N] = incl;                    // grand total
}

__global__ void __launch_bounds__(1024) scanC_k() {
    int t = blockIdx.y;
    int N, E; int *deg, *rp, *cur, *col;
    csr_ptrs(t, N, E, deg, rp, cur, col);
    int nb = (N + 1023) >> 10;
    if ((int)blockIdx.x >= nb) return;
    int i = blockIdx.x * 1024 + threadIdx.x;
    if (i < N) {
        int v = rp[i] + g_bs[t * SCB + blockIdx.x];
        rp[i] = v;
        cur[i] = v;
    }
}

__global__ void fill_k(EP6 ep) {
    int t = blockIdx.y;
    int N, E; int *deg, *rp, *cur, *col;
    csr_ptrs(t, N, E, deg, rp, cur, col);
    int base = (blockIdx.x * 256 + threadIdx.x) * 4;
    if (base >= E) return;
    int4 s4 = *(const int4*)(ep.p[t] + base);
    int4 d4 = *(const int4*)(ep.p[t] + E + base);
    int p0 = atomicAdd(&cur[d4.x], 1);
    int p1 = atomicAdd(&cur[d4.y], 1);
    int p2 = atomicAdd(&cur[d4.z], 1);
    int p3 = atomicAdd(&cur[d4.w], 1);
    col[p0] = s4.x; col[p1] = s4.y; col[p2] = s4.z; col[p3] = s4.w;
}

// ------------- dense phase: 2 edge-types per block, tf32 mma, fp16 H out -------------
__global__ void __launch_bounds__(256) gemm6_k(const float* __restrict__ X, GP6 gp) {
    __shared__ __align__(16) float Xs[128][36];
    __shared__ __align__(16) float WsT[2][64][36];
    int pair = blockIdx.y;                  // types 2*pair, 2*pair+1
    int tid = threadIdx.x;
    int wid = tid >> 5, lane = tid & 31;
    int g = lane >> 2, tg = lane & 3;
    int m0 = blockIdx.x * 128;
    int mw = wid * 16;

    float acc[2][8][4];
    #pragma unroll
    for (int u = 0; u < 2; u++)
        #pragma unroll
        for (int j = 0; j < 8; j++)
            #pragma unroll
            for (int c = 0; c < 4; c++) acc[u][j][c] = 0.f;

    for (int kb = 0; kb < 128; kb += 32) {
        #pragma unroll
        for (int q = 0; q < 4; q++) {
            int f = tid + q * 256;
            int row = f >> 3, c4 = (f & 7) * 4;
            int gr = m0 + row;
            float4 v = make_float4(0.f, 0.f, 0.f, 0.f);
            if (gr < NSKU) v = *(const float4*)(X + (size_t)gr * 128 + kb + c4);
            cvt4(v);
            *(float4*)&Xs[row][c4] = v;
        }
        #pragma unroll
        for (int u = 0; u < 2; u++) {
            const float* __restrict__ W = gp.W[2 * pair + u];
            #pragma unroll
            for (int q = 0; q < 2; q++) {
                int f = tid + q * 256;
                int k = f >> 4, n4 = (f & 15) * 4;
                float4 v = *(const float4*)(W + (size_t)(kb + k) * 64 + n4);
                cvt4(v);
                WsT[u][n4 + 0][k] = v.x; WsT[u][n4 + 1][k] = v.y;
                WsT[u][n4 + 2][k] = v.z; WsT[u][n4 + 3][k] = v.w;
            }
        }
        __syncthreads();
        #pragma unroll
        for (int ks = 0; ks < 4; ks++) {
            int k0 = ks * 8 + 2 * tg;
            float2 a02 = *(const float2*)&Xs[mw + g][k0];
            float2 a13 = *(const float2*)&Xs[mw + g + 8][k0];
            u32 a0 = __float_as_uint(a02.x), a1 = __float_as_uint(a13.x);
            u32 a2 = __float_as_uint(a02.y), a3 = __float_as_uint(a13.y);
            #pragma unroll
            for (int j = 0; j < 8; j++) {
                float2 b0 = *(const float2*)&WsT[0][8 * j + g][k0];
                mma_tf32(acc[0][j], a0, a1, a2, a3,
                         __float_as_uint(b0.x), __float_as_uint(b0.y));
                float2 b1 = *(const float2*)&WsT[1][8 * j + g][k0];
                mma_tf32(acc[1][j], a0, a1, a2, a3,
                         __float_as_uint(b1.x), __float_as_uint(b1.y));
            }
        }
        __syncthreads();
    }

    int r0 = m0 + mw + g;
    int r1 = r0 + 8;
    #pragma unroll
    for (int u = 0; u < 2; u++) {
        int t = 2 * pair + u;
        __half2* Hh = (__half2*)(g_Hh + (size_t)t * NSKU * 64);
        const float* av = gp.a[t];
        float* Sst = g_Ss + (size_t)t * NSKU * 4;
        float* Sdt = (t < 4) ? (g_SdI + (size_t)t * NSKU * 4) : 0;

        #pragma unroll
        for (int j = 0; j < 8; j++) {
            int c2 = 4 * j + tg;   // half2 index within row
            if (r0 < NSKU) Hh[(size_t)r0 * 32 + c2] = __floats2half2_rn(acc[u][j][0], acc[u][j][1]);
            if (r1 < NSKU) Hh[(size_t)r1 * 32 + c2] = __floats2half2_rn(acc[u][j][2], acc[u][j][3]);
        }

        float2 sA0 = *(const float2*)(av + 2 * tg);
        float2 sA1 = *(const float2*)(av + 8 + 2 * tg);
        float2 dA0 = *(const float2*)(av + 16 + 2 * tg);
        float2 dA1 = *(const float2*)(av + 24 + 2 * tg);
        #pragma unroll
        for (int h = 0; h < 4; h++) {
            float p0 = acc[u][2*h][0] * sA0.x + acc[u][2*h][1] * sA0.y
                     + acc[u][2*h+1][0] * sA1.x + acc[u][2*h+1][1] * sA1.y;
            float p1 = acc[u][2*h][2] * sA0.x + acc[u][2*h][3] * sA0.y
                     + acc[u][2*h+1][2] * sA1.x + acc[u][2*h+1][3] * sA1.y;
            float q0 = acc[u][2*h][0] * dA0.x + acc[u][2*h][1] * dA0.y
                     + acc[u][2*h+1][0] * dA1.x + acc[u][2*h+1][1] * dA1.y;
            float q1 = acc[u][2*h][2] * dA0.x + acc[u][2*h][3] * dA0.y
                     + acc[u][2*h+1][2] * dA1.x + acc[u][2*h+1][3] * dA1.y;
            #pragma unroll
            for (int o = 1; o < 4; o <<= 1) {
                p0 += __shfl_xor_sync(0xffffffffu, p0, o);
                p1 += __shfl_xor_sync(0xffffffffu, p1, o);
                q0 += __shfl_xor_sync(0xffffffffu, q0, o);
                q1 += __shfl_xor_sync(0xffffffffu, q1, o);
            }
            if (tg == 0) {
                if (r0 < NSKU) { Sst[r0 * 4 + h] = p0; if (Sdt) Sdt[r0 * 4 + h] = q0; }
                if (r1 < NSKU) { Sst[r1 * 4 + h] = p1; if (Sdt) Sdt[r1 * 4 + h] = q1; }
            }
        }
    }
}

// ------------- dst-side scores for cross types (tiny matvec) -------------
__global__ void dstscore_k(const float* __restrict__ X, const float* __restrict__ W,
                           const float* __restrict__ av, int which, int N) {
    float* S = which ? g_Ssup : g_Swh;
    int n = blockIdx.x;
    if (n >= N) return;
    int d = threadIdx.x;
    const float* xr = X + (size_t)n * 128;
    float h = 0.f;
    for (int k = 0; k < 128; k++) h += xr[k] * W[k * 64 + d];
    float p = h * av[16 + (d & 15)];
    #pragma unroll
    for (int o = 1; o < 16; o <<= 1) p += __shfl_xor_sync(0xffffffffu, p, o);
    if ((d & 15) == 0) S[n * 4 + (d >> 4)] = p;
}

// ------------- edge aggregation: one warp per dst node, fp16 H, unroll-2 -------------
__global__ void agg_intra_k() {
    int warp = (blockIdx.x * blockDim.x + threadIdx.x) >> 5;
    int lane = threadIdx.x & 31;
    if (warp >= NSKU) return;
    int dst = warp;
    int head = lane >> 3;
    float2 tot = make_float2(0.f, 0.f);
    #pragma unroll
    for (int t = 0; t < 4; t++) {
        const int* rp = g_rp + t * (NSKU + 1);
        const int* col = g_col + t * EINTRA;
        const float* Ss = g_Ss + (size_t)t * NSKU * 4;
        const float* Sd = g_SdI + (size_t)t * NSKU * 4;
        const __half2* Hh = (const __half2*)(g_Hh + (size_t)t * NSKU * 64);
        float sd = Sd[dst * 4 + head];
        float2 acc = make_float2(0.f, 0.f);
        float den = 0.f;
        int e = rp[dst], e1 = rp[dst + 1];
        for (; e + 1 < e1; e += 2) {
            int s0 = __ldg(&col[e]);
            int s1 = __ldg(&col[e + 1]);
            float x0 = __ldg(&Ss[s0 * 4 + head]) + sd;
            float x1 = __ldg(&Ss[s1 * 4 + head]) + sd;
            float2 h0 = __half22float2(Hh[(size_t)s0 * 32 + lane]);
            float2 h1 = __half22float2(Hh[(size_t)s1 * 32 + lane]);
            float el0 = x0 > 0.f ? x0 : (__expf(x0) - 1.f);
            float el1 = x1 > 0.f ? x1 : (__expf(x1) - 1.f);
            float w0 = __expf(el0), w1 = __expf(el1);
            acc.x += w0 * h0.x + w1 * h1.x;
            acc.y += w0 * h0.y + w1 * h1.y;
            den += w0 + w1;
        }
        if (e < e1) {
            int s0 = __ldg(&col[e]);
            float x0 = __ldg(&Ss[s0 * 4 + head]) + sd;
            float2 h0 = __half22float2(Hh[(size_t)s0 * 32 + lane]);
            float el0 = x0 > 0.f ? x0 : (__expf(x0) - 1.f);
            float w0 = __expf(el0);
            acc.x += w0 * h0.x; acc.y += w0 * h0.y; den += w0;
        }
        float inv = 1.f / (den + 1e-12f);
        tot.x += acc.x * inv; tot.y += acc.y * inv;
    }
    *(float2*)(g_OA + (size_t)dst * 64 + 2 * lane) = tot;
}

__global__ void agg_cross_k(int t, int N) {
    int warp = (blockIdx.x * blockDim.x + threadIdx.x) >> 5;
    int lane = threadIdx.x & 31;
    if (warp >= N) return;
    int dst = warp;
    int head = lane >> 3;
    const int* rp = g_rp + 4 * (NSKU + 1) + (t == 5 ? (NWH + 1) : 0);
    const int* col = g_col + 4 * EINTRA + (t == 5 ? ECROSS : 0);
    const float* Ss = g_Ss + (size_t)t * NSKU * 4;
    const float* Sd = (t == 4) ? g_Swh : g_Ssup;
    const __half2* Hh = (const __half2*)(g_Hh + (size_t)t * NSKU * 64);
    float* Out = (t == 4) ? g_OBwh : g_OBsup;
    float sd = Sd[dst * 4 + head];
    float2 acc = make_float2(0.f, 0.f);
    float den = 0.f;
    int e = rp[dst], e1 = rp[dst + 1];
    for (; e + 1 < e1; e += 2) {
        int s0 = __ldg(&col[e]);
        int s1 = __ldg(&col[e + 1]);
        float x0 = __ldg(&Ss[s0 * 4 + head]) + sd;
        float x1 = __ldg(&Ss[s1 * 4 + head]) + sd;
        float2 h0 = __half22float2(Hh[(size_t)s0 * 32 + lane]);
        float2 h1 = __half22float2(Hh[(size_t)s1 * 32 + lane]);
        float el0 = x0 > 0.f ? x0 : (__expf(x0) - 1.f);
        float el1 = x1 > 0.f ? x1 : (__expf(x1) - 1.f);
        float w0 = __expf(el0), w1 = __expf(el1);
        acc.x += w0 * h0.x + w1 * h1.x;
        acc.y += w0 * h0.y + w1 * h1.y;
        den += w0 + w1;
    }
    if (e < e1) {
        int s0 = __ldg(&col[e]);
        float x0 = __ldg(&Ss[s0 * 4 + head]) + sd;
        float2 h0 = __half22float2(Hh[(size_t)s0 * 32 + lane]);
        float el0 = x0 > 0.f ? x0 : (__expf(x0) - 1.f);
        float w0 = __expf(el0);
        acc.x += w0 * h0.x; acc.y += w0 * h0.y; den += w0;
    }
    float inv = 1.f / (den + 1e-12f);
    *(float2*)(Out + (size_t)dst * 64 + 2 * lane) = make_float2(acc.x * inv, acc.y * inv);
}

// ------------- finish: tf32 mma GEMM [G|X] @ [PW;RW], fused LayerNorm -------------
__global__ void __launch_bounds__(256) finishT_k(
        const float* __restrict__ X, const float* __restrict__ PW,
        const float* __restrict__ RW, const float* __restrict__ pb,
        const float* __restrict__ lg, const float* __restrict__ lb,
        float* __restrict__ out, int N, int which) {
    const float* __restrict__ G = (which == 0) ? g_OA : (which == 1) ? g_OBwh : g_OBsup;
    __shared__ __align__(16) float As[128][36];
    __shared__ __align__(16) float BsT[64][36];
    int tid = threadIdx.x;
    int wid = tid >> 5, lane = tid & 31;
    int g = lane >> 2, tg = lane & 3;
    int m0 = blockIdx.x * 128;
    int mw = wid * 16;

    float acc[8][4];
    #pragma unroll
    for (int j = 0; j < 8; j++)
        #pragma unroll
        for (int c = 0; c < 4; c++) acc[j][c] = 0.f;

    for (int kb = 0; kb < 192; kb += 32) {
        #pragma unroll
        for (int q = 0; q < 4; q++) {
            int f = tid + q * 256;
            int row = f >> 3, c4 = (f & 7) * 4;
            int gr = m0 + row;
            int k = kb + c4;
            float4 v = make_float4(0.f, 0.f, 0.f, 0.f);
            if (gr < N) {
                if (k < 64) v = *(const float4*)(G + (size_t)gr * 64 + k);
                else        v = *(const float4*)(X + (size_t)gr * 128 + (k - 64));
            }
            cvt4(v);
            *(float4*)&As[row][c4] = v;
        }
        #pragma unroll
        for (int q = 0; q < 2; q++) {
            int f = tid + q * 256;
            int k = f >> 4, n4 = (f & 15) * 4;
            int gk = kb + k;
            const float* src = (gk < 64) ? (PW + (size_t)gk * 64)
                                         : (RW + (size_t)(gk - 64) * 64);
            float4 v = *(const float4*)(src + n4);
            cvt4(v);
            BsT[n4 + 0][k] = v.x; BsT[n4 + 1][k] = v.y;
            BsT[n4 + 2][k] = v.z; BsT[n4 + 3][k] = v.w;
        }
        __syncthreads();
        #pragma unroll
        for (int ks = 0; ks < 4; ks++) {
            int k0 = ks * 8 + 2 * tg;
            float2 a02 = *(const float2*)&As[mw + g][k0];
            float2 a13 = *(const float2*)&As[mw + g + 8][k0];
            u32 a0 = __float_as_uint(a02.x), a1 = __float_as_uint(a13.x);
            u32 a2 = __float_as_uint(a02.y), a3 = __float_as_uint(a13.y);
            #pragma unroll
            for (int j = 0; j < 8; j++) {
                float2 b01 = *(const float2*)&BsT[8 * j + g][k0];
                mma_tf32(acc[j], a0, a1, a2, a3,
                         __float_as_uint(b01.x), __float_as_uint(b01.y));
            }
        }
        __syncthreads();
    }

    // epilogue: + bias, LayerNorm over 64 cols (4-lane tg-group reduction), store
    int r0 = m0 + mw + g;
    int r1 = r0 + 8;
    float y0[8][2], y1[8][2];
    float s1a = 0.f, s2a = 0.f, s1b = 0.f, s2b = 0.f;
    #pragma unroll
    for (int j = 0; j < 8; j++) {
        float2 pbv = *(const float2*)(pb + 8 * j + 2 * tg);
        y0[j][0] = acc[j][0] + pbv.x; y0[j][1] = acc[j][1] + pbv.y;
        y1[j][0] = acc[j][2] + pbv.x; y1[j][1] = acc[j][3] + pbv.y;
        s1a += y0[j][0] + y0[j][1];
        s2a += y0[j][0] * y0[j][0] + y0[j][1] * y0[j][1];
        s1b += y1[j][0] + y1[j][1];
        s2b += y1[j][0] * y1[j][0] + y1[j][1] * y1[j][1];
    }
    #pragma unroll
    for (int o = 1; o < 4; o <<= 1) {
        s1a += __shfl_xor_sync(0xffffffffu, s1a, o);
        s2a += __shfl_xor_sync(0xffffffffu, s2a, o);
        s1b += __shfl_xor_sync(0xffffffffu, s1b, o);
        s2b += __shfl_xor_sync(0xffffffffu, s2b, o);
    }
    float mua = s1a * (1.f / 64.f);
    float vara = s2a * (1.f / 64.f) - mua * mua;
    float inva = rsqrtf(vara + 1e-5f);
    float mub = s1b * (1.f / 64.f);
    float varb = s2b * (1.f / 64.f) - mub * mub;
    float invb = rsqrtf(varb + 1e-5f);
    #pragma unroll
    for (int j = 0; j < 8; j++) {
        int c = 8 * j + 2 * tg;
        float2 gv = *(const float2*)(lg + c);
        float2 bv = *(const float2*)(lb + c);
        if (r0 < N)
            *(float2*)(out + (size_t)r0 * 64 + c) =
                make_float2((y0[j][0] - mua) * inva * gv.x + bv.x,
                            (y0[j][1] - mua) * inva * gv.y + bv.y);
        if (r1 < N)
            *(float2*)(out + (size_t)r1 * 64 + c) =
                make_float2((y1[j][0] - mub) * invb * gv.x + bv.x,
                            (y1[j][1] - mub) * invb * gv.y + bv.y);
    }
}

// ------------- launch (3-stream DAG) -------------
extern "C" void kernel_launch(void* const* d_in, const int* in_sizes, int n_in,
                              void* d_out, int out_size) {
    const float* x_sku = (const float*)d_in[0];
    const float* x_wh  = (const float*)d_in[1];
    const float* x_sup = (const float*)d_in[2];
    GP6 gp; EP6 ep;
    for (int i = 0; i < 6; i++) {
        gp.W[i] = (const float*)d_in[3 + 2 * i];
        gp.a[i] = (const float*)d_in[4 + 2 * i];
    }
    const float* proj_W = (const float*)d_in[15];
    const float* proj_b = (const float*)d_in[16];
    const float* ln_g   = (const float*)d_in[17];
    const float* ln_b   = (const float*)d_in[18];
    const float* res_W  = (const float*)d_in[19];
    for (int i = 0; i < 6; i++) ep.p[i] = (const int*)d_in[20 + i];
    float* out = (float*)d_out;

    static cudaStream_t s1 = 0, s2 = 0;
    static cudaEvent_t ev_root = 0, ev_csr = 0, ev_gemm = 0, ev_s2 = 0;
    if (!s1) {
        cudaStreamCreateWithFlags(&s1, cudaStreamNonBlocking);
        cudaStreamCreateWithFlags(&s2, cudaStreamNonBlocking);
        cudaEventCreateWithFlags(&ev_root, cudaEventDisableTiming);
        cudaEventCreateWithFlags(&ev_csr, cudaEventDisableTiming);
        cudaEventCreateWithFlags(&ev_gemm, cudaEventDisableTiming);
        cudaEventCreateWithFlags(&ev_s2, cudaEventDisableTiming);
    }

    // fork
    cudaEventRecord(ev_root, 0);
    cudaStreamWaitEvent(s1, ev_root, 0);
    cudaStreamWaitEvent(s2, ev_root, 0);

    // S1: CSR build
    zero_deg_k<<<(TOTN + 255) / 256, 256, 0, s1>>>();
    count_k<<<dim3((EINTRA / 4 + 255) / 256, 6), 256, 0, s1>>>(ep);
    scanA_k<<<dim3(SCB, 6), 1024, 0, s1>>>();
    scanB_k<<<6, 128, 0, s1>>>();
    scanC_k<<<dim3(SCB, 6), 1024, 0, s1>>>();
    fill_k<<<dim3((EINTRA / 4 + 255) / 256, 6), 256, 0, s1>>>(ep);
    cudaEventRecord(ev_csr, s1);

    // S2: dst-side scores for cross types
    dstscore_k<<<NWH, 64, 0, s2>>>(x_wh, gp.W[4], gp.a[4], 0, NWH);
    dstscore_k<<<NSUP, 64, 0, s2>>>(x_sup, gp.W[5], gp.a[5], 1, NSUP);

    // S0: dense phase (tf32 tensor cores, 2 types per block)
    gemm6_k<<<dim3((NSKU + 127) / 128, 3), 256>>>(x_sku, gp);
    cudaEventRecord(ev_gemm, 0);

    // S0: sku chain
    cudaStreamWaitEvent(0, ev_csr, 0);
    agg_intra_k<<<(NSKU * 32 + 255) / 256, 256>>>();
    finishT_k<<<(NSKU + 127) / 128, 256>>>(x_sku, proj_W, res_W, proj_b, ln_g, ln_b,
                                           out, NSKU, 0);

    // S2: cross chains
    cudaStreamWaitEvent(s2, ev_gemm, 0);
    cudaStreamWaitEvent(s2, ev_csr, 0);
    agg_cross_k<<<(NWH * 32 + 255) / 256, 256, 0, s2>>>(4, NWH);
    agg_cross_k<<<(NSUP * 32 + 255) / 256, 256, 0, s2>>>(5, NSUP);
    finishT_k<<<(NWH + 127) / 128, 256, 0, s2>>>(x_wh, proj_W + 64 * 64, res_W, proj_b,
                                                 ln_g, ln_b, out + (size_t)NSKU * 64, NWH, 1);
    finishT_k<<<(NSUP + 127) / 128, 256, 0, s2>>>(x_sup, proj_W + 64 * 64, res_W, proj_b,
                                                  ln_g, ln_b, out + (size_t)(NSKU + NWH) * 64,
                                                  NSUP, 2);
    cudaEventRecord(ev_s2, s2);

    // join
    cudaStreamWaitEvent(0, ev_s2, 0);
}